// round 2
// baseline (speedup 1.0000x reference)
#include <cuda_runtime.h>
#include <cuda_bf16.h>
#include <cstddef>

// Problem constants
#define BATCH 4
#define C_IN  256
#define CI    128
#define NPIX  4096   // 64*64

// ---------------------------------------------------------------------------
// Scratch (allocation-free: __device__ globals)
// ---------------------------------------------------------------------------
__device__ float g_T[(size_t)BATCH * NPIX * CI];  // theta(a): [B][N][Ci]
__device__ float g_P[(size_t)BATCH * CI * NPIX];  // phi(b)  : [B][Ci][N]
__device__ float g_G[(size_t)BATCH * NPIX * CI];  // g(b)    : [B][N][Ci]
__device__ float g_Y[(size_t)BATCH * NPIX * CI];  // y       : [B][N][Ci]

// ---------------------------------------------------------------------------
// Projection: out = w[Ci,C] @ x[b][C,N] + bias
//   transOut=1 -> out[b][n][ci] ; transOut=0 -> out[b][ci][n]
// CTA: (n-tile of 64) x (batch). Computes all 128 ci.
// ---------------------------------------------------------------------------
__global__ __launch_bounds__(256)
void proj_kernel(const float* __restrict__ x, const float* __restrict__ w,
                 const float* __restrict__ bias, float* __restrict__ out,
                 int transOut) {
    __shared__ float sX[32][64];    // x tile   [c][n]
    __shared__ float sW[128][32];   // w tile   [ci][c]

    const int bb = blockIdx.y;
    const int n0 = blockIdx.x * 64;
    const int t  = threadIdx.x;
    const int tx = t & 15, ty = t >> 4;     // 16x16 threads

    float acc[8][4];
#pragma unroll
    for (int i = 0; i < 8; i++)
#pragma unroll
        for (int j = 0; j < 4; j++) acc[i][j] = 0.f;

    const float* xb = x + (size_t)bb * C_IN * NPIX;

    for (int c0 = 0; c0 < C_IN; c0 += 32) {
        // load sX (2048 elems / 8 per thread)
#pragma unroll
        for (int i = 0; i < 8; i++) {
            int idx = t + i * 256;
            int c = idx >> 6, n = idx & 63;
            sX[c][n] = xb[(size_t)(c0 + c) * NPIX + n0 + n];
        }
        // load sW (4096 elems / 16 per thread)
#pragma unroll
        for (int i = 0; i < 16; i++) {
            int idx = t + i * 256;
            int ci = idx >> 5, c = idx & 31;
            sW[ci][c] = w[ci * C_IN + c0 + c];
        }
        __syncthreads();

#pragma unroll 8
        for (int k = 0; k < 32; k++) {
            float wf[8];
#pragma unroll
            for (int i = 0; i < 8; i++) wf[i] = sW[8 * ty + i][k];
            float4 xv = *(const float4*)&sX[k][4 * tx];
            float xf[4] = {xv.x, xv.y, xv.z, xv.w};
#pragma unroll
            for (int i = 0; i < 8; i++)
#pragma unroll
                for (int j = 0; j < 4; j++) acc[i][j] += wf[i] * xf[j];
        }
        __syncthreads();
    }

    float bv[8];
#pragma unroll
    for (int i = 0; i < 8; i++) bv[i] = bias[8 * ty + i];

    if (transOut) {
        // out[b][n][ci]
#pragma unroll
        for (int j = 0; j < 4; j++) {
            int n = n0 + 4 * tx + j;
            float* o = out + ((size_t)bb * NPIX + n) * CI + 8 * ty;
            float4 v0 = make_float4(acc[0][j] + bv[0], acc[1][j] + bv[1],
                                    acc[2][j] + bv[2], acc[3][j] + bv[3]);
            float4 v1 = make_float4(acc[4][j] + bv[4], acc[5][j] + bv[5],
                                    acc[6][j] + bv[6], acc[7][j] + bv[7]);
            *(float4*)o       = v0;
            *(float4*)(o + 4) = v1;
        }
    } else {
        // out[b][ci][n]
#pragma unroll
        for (int i = 0; i < 8; i++) {
            int ci = 8 * ty + i;
            float* o = out + ((size_t)bb * CI + ci) * NPIX + n0 + 4 * tx;
            *(float4*)o = make_float4(acc[i][0] + bv[i], acc[i][1] + bv[i],
                                      acc[i][2] + bv[i], acc[i][3] + bv[i]);
        }
    }
}

// ---------------------------------------------------------------------------
// Fused attention: Y[b][n][:] = sum_m ( T[b][n][:].P[b][:][m] / N ) * G[b][m][:]
// Never materializes f. CTA: 64 rows of n, loops over m in tiles of 64.
// Shared: sT 32KB + sP 32KB + sG 32KB + sS 16KB = 112KB (dynamic).
// ---------------------------------------------------------------------------
__global__ __launch_bounds__(256)
void attn_kernel(const float* __restrict__ T, const float* __restrict__ P,
                 const float* __restrict__ G, float* __restrict__ Y) {
    extern __shared__ float smem[];
    float* sT = smem;                 // [64][128]
    float* sP = sT + 64 * 128;        // [128][64]
    float* sG = sP + 128 * 64;        // [64][128]
    float* sS = sG + 64 * 128;        // [64][64]

    const int bb = blockIdx.y;
    const int n0 = blockIdx.x * 64;
    const int t  = threadIdx.x;
    const int tx = t & 15, ty = t >> 4;

    const float* Tb = T + ((size_t)bb * NPIX + n0) * CI;  // contiguous [64][128]
    const float* Pb = P + (size_t)bb * CI * NPIX;
    const float* Gb = G + (size_t)bb * NPIX * CI;

    // load sT once (2048 float4 / 8 per thread)
#pragma unroll
    for (int i = 0; i < 8; i++) {
        int idx = t + i * 256;
        ((float4*)sT)[idx] = ((const float4*)Tb)[idx];
    }

    float accY[4][8];
#pragma unroll
    for (int i = 0; i < 4; i++)
#pragma unroll
        for (int j = 0; j < 8; j++) accY[i][j] = 0.f;

    const float invN = 1.0f / (float)NPIX;

    for (int m0 = 0; m0 < NPIX; m0 += 64) {
        // load sP[ci][m] : per-ci rows strided by NPIX in global
#pragma unroll
        for (int i = 0; i < 8; i++) {
            int idx = t + i * 256;            // float4 index over [128][16]
            int ci = idx >> 4, m4 = idx & 15;
            ((float4*)sP)[ci * 16 + m4] =
                *(const float4*)&Pb[(size_t)ci * NPIX + m0 + 4 * m4];
        }
        // load sG[m][ci] : contiguous block [64][128]
        const float4* Gsrc = (const float4*)(Gb + (size_t)m0 * CI);
#pragma unroll
        for (int i = 0; i < 8; i++) {
            int idx = t + i * 256;
            ((float4*)sG)[idx] = Gsrc[idx];
        }
        __syncthreads();

        // S[64][64] = T @ P  (thread: rows 4ty+i, cols 4tx+j)
        float accS[4][4];
#pragma unroll
        for (int i = 0; i < 4; i++)
#pragma unroll
            for (int j = 0; j < 4; j++) accS[i][j] = 0.f;

#pragma unroll 4
        for (int k = 0; k < 128; k++) {
            float af[4];
#pragma unroll
            for (int i = 0; i < 4; i++) af[i] = sT[(4 * ty + i) * 128 + k];
            float4 bvv = *(float4*)&sP[k * 64 + 4 * tx];
            float bf[4] = {bvv.x, bvv.y, bvv.z, bvv.w};
#pragma unroll
            for (int i = 0; i < 4; i++)
#pragma unroll
                for (int j = 0; j < 4; j++) accS[i][j] += af[i] * bf[j];
        }
#pragma unroll
        for (int i = 0; i < 4; i++) {
            *(float4*)&sS[(4 * ty + i) * 64 + 4 * tx] =
                make_float4(accS[i][0] * invN, accS[i][1] * invN,
                            accS[i][2] * invN, accS[i][3] * invN);
        }
        __syncthreads();

        // Y += S @ G  (thread: rows 4ty+i, cols 8tx+j)
#pragma unroll 2
        for (int k = 0; k < 64; k++) {
            float af[4];
#pragma unroll
            for (int i = 0; i < 4; i++) af[i] = sS[(4 * ty + i) * 64 + k];
            float4 b0 = *(float4*)&sG[k * 128 + 8 * tx];
            float4 b1 = *(float4*)&sG[k * 128 + 8 * tx + 4];
            float bf[8] = {b0.x, b0.y, b0.z, b0.w, b1.x, b1.y, b1.z, b1.w};
#pragma unroll
            for (int i = 0; i < 4; i++)
#pragma unroll
                for (int j = 0; j < 8; j++) accY[i][j] += af[i] * bf[j];
        }
        __syncthreads();
    }

    // write Y[b][n0+4ty+i][8tx + 0..7]
#pragma unroll
    for (int i = 0; i < 4; i++) {
        float* o = Y + ((size_t)bb * NPIX + n0 + 4 * ty + i) * CI + 8 * tx;
        *(float4*)o       = make_float4(accY[i][0], accY[i][1], accY[i][2], accY[i][3]);
        *(float4*)(o + 4) = make_float4(accY[i][4], accY[i][5], accY[i][6], accY[i][7]);
    }
}

// ---------------------------------------------------------------------------
// Final: out[b][c][n] = A[c] * (W_w[c,:] . Y[b][n][:]) + Bb[c]
//   A = gamma * rsqrt(var+eps), Bb = beta - mean*A
// CTA tile: [64 c][64 n], full K=128.
// ---------------------------------------------------------------------------
__global__ __launch_bounds__(256)
void final_kernel(const float* __restrict__ Y, const float* __restrict__ Ww,
                  const float* __restrict__ gamma, const float* __restrict__ beta,
                  const float* __restrict__ mean, const float* __restrict__ var,
                  float* __restrict__ out) {
    __shared__ float sY[64][129];   // padded: scalar fills, 2-way reads
    __shared__ float sW[64][128];

    const int bb = blockIdx.z;
    const int c0 = blockIdx.y * 64;
    const int n0 = blockIdx.x * 64;
    const int t  = threadIdx.x;
    const int tx = t & 15, ty = t >> 4;

    // load sW (float4)
#pragma unroll
    for (int i = 0; i < 8; i++) {
        int idx = t + i * 256;
        int r = idx >> 5, c4 = idx & 31;
        *(float4*)&sW[r][4 * c4] = *(const float4*)&Ww[(c0 + r) * CI + 4 * c4];
    }
    // load sY (scalar, padded rows)
    const float* Yb = Y + ((size_t)bb * NPIX + n0) * CI;
#pragma unroll
    for (int i = 0; i < 32; i++) {
        int idx = t + i * 256;
        int n = idx >> 7, k = idx & 127;
        sY[n][k] = Yb[(size_t)n * CI + k];
    }
    __syncthreads();

    float acc[4][4];
#pragma unroll
    for (int i = 0; i < 4; i++)
#pragma unroll
        for (int j = 0; j < 4; j++) acc[i][j] = 0.f;

#pragma unroll 4
    for (int k = 0; k < 128; k++) {
        float wf[4], yf[4];
#pragma unroll
        for (int i = 0; i < 4; i++) wf[i] = sW[4 * ty + i][k];
#pragma unroll
        for (int j = 0; j < 4; j++) yf[j] = sY[4 * tx + j][k];
#pragma unroll
        for (int i = 0; i < 4; i++)
#pragma unroll
            for (int j = 0; j < 4; j++) acc[i][j] += wf[i] * yf[j];
    }

#pragma unroll
    for (int i = 0; i < 4; i++) {
        int c = c0 + 4 * ty + i;
        float inv = rsqrtf(var[c] + 1e-5f);
        float A  = gamma[c] * inv;
        float Bb = beta[c] - mean[c] * A;
        float* o = out + ((size_t)bb * C_IN + c) * NPIX + n0 + 4 * tx;
        *(float4*)o = make_float4(acc[i][0] * A + Bb, acc[i][1] * A + Bb,
                                  acc[i][2] * A + Bb, acc[i][3] * A + Bb);
    }
}

// ---------------------------------------------------------------------------
// Launch
// ---------------------------------------------------------------------------
extern "C" void kernel_launch(void* const* d_in, const int* in_sizes, int n_in,
                              void* d_out, int out_size) {
    const float* a       = (const float*)d_in[0];
    const float* b       = (const float*)d_in[1];
    const float* theta_w = (const float*)d_in[2];
    const float* theta_b = (const float*)d_in[3];
    const float* phi_w   = (const float*)d_in[4];
    const float* phi_b   = (const float*)d_in[5];
    const float* g_w     = (const float*)d_in[6];
    const float* g_b     = (const float*)d_in[7];
    const float* W_w     = (const float*)d_in[8];
    const float* bn_g    = (const float*)d_in[9];
    const float* bn_be   = (const float*)d_in[10];
    const float* bn_m    = (const float*)d_in[11];
    const float* bn_v    = (const float*)d_in[12];
    float* out = (float*)d_out;

    float *T, *P, *G, *Y;
    cudaGetSymbolAddress((void**)&T, g_T);
    cudaGetSymbolAddress((void**)&P, g_P);
    cudaGetSymbolAddress((void**)&G, g_G);
    cudaGetSymbolAddress((void**)&Y, g_Y);

    dim3 projGrid(NPIX / 64, BATCH);
    proj_kernel<<<projGrid, 256>>>(a, theta_w, theta_b, T, 1);
    proj_kernel<<<projGrid, 256>>>(b, phi_w,   phi_b,   P, 0);
    proj_kernel<<<projGrid, 256>>>(b, g_w,     g_b,     G, 1);

    static bool attr_set = false;
    if (!attr_set) {
        cudaFuncSetAttribute(attn_kernel,
                             cudaFuncAttributeMaxDynamicSharedMemorySize,
                             114688);
        attr_set = true;
    }
    dim3 attnGrid(NPIX / 64, BATCH);
    attn_kernel<<<attnGrid, 256, 114688>>>(T, P, G, Y);

    dim3 finGrid(NPIX / 64, C_IN / 64, BATCH);
    final_kernel<<<finGrid, 256>>>(Y, W_w, bn_g, bn_be, bn_m, bn_v, out);
}

// round 7
// speedup vs baseline: 3.1472x; 3.1472x over previous
#include <cuda_runtime.h>
#include <cuda_bf16.h>
#include <cstdint>
#include <cstddef>

// Problem constants
#define BATCH 4
#define C_IN  256
#define CI    128
#define NPIX  4096   // 64*64
#define NT    128    // n-rows per attn CTA
#define MT    64     // m-chunk
#define NCHUNK (NPIX / MT)   // 64

// ---------------------------------------------------------------------------
// Scratch (allocation-free: __device__ globals)
// ---------------------------------------------------------------------------
__device__ __nv_bfloat16 g_Thi[(size_t)BATCH * NPIX * CI];  // theta(a) [B][n][ci]
__device__ __nv_bfloat16 g_Tlo[(size_t)BATCH * NPIX * CI];
__device__ __nv_bfloat16 g_Phh[(size_t)BATCH * NPIX * CI];  // phi(b)   [B][m][ci]
__device__ __nv_bfloat16 g_Phl[(size_t)BATCH * NPIX * CI];
__device__ __nv_bfloat16 g_Ghi[(size_t)BATCH * CI * NPIX];  // g(b)     [B][ci][m]
__device__ __nv_bfloat16 g_Glo[(size_t)BATCH * CI * NPIX];
__device__ float         g_Y  [(size_t)BATCH * NPIX * CI];  // y        [B][n][ci]

// ---------------------------------------------------------------------------
// PTX helpers (baseline features only: valid under compute_103)
// ---------------------------------------------------------------------------
__device__ __forceinline__ uint32_t smem_u32(const void* p) {
    uint32_t a;
    asm("{ .reg .u64 t; cvta.to.shared.u64 t, %1; cvt.u32.u64 %0, t; }"
        : "=r"(a) : "l"(p));
    return a;
}

#define LDM_X4(r, a)                                                          \
    asm volatile("ldmatrix.sync.aligned.m8n8.x4.shared.b16 {%0,%1,%2,%3}, [%4];" \
        : "=r"((r)[0]), "=r"((r)[1]), "=r"((r)[2]), "=r"((r)[3]) : "r"(a))

__device__ __forceinline__ void mma16816(float* d, const uint32_t* a,
                                         uint32_t b0, uint32_t b1) {
    asm volatile("mma.sync.aligned.m16n8k16.row.col.f32.bf16.bf16.f32 "
        "{%0,%1,%2,%3}, {%4,%5,%6,%7}, {%8,%9}, {%0,%1,%2,%3};"
        : "+f"(d[0]), "+f"(d[1]), "+f"(d[2]), "+f"(d[3])
        : "r"(a[0]), "r"(a[1]), "r"(a[2]), "r"(a[3]), "r"(b0), "r"(b1));
}

#define CP16(dst, src)                                                        \
    asm volatile("cp.async.cg.shared.global [%0], [%1], 16;"                  \
                 :: "r"(dst), "l"(src) : "memory")
#define CP_COMMIT() asm volatile("cp.async.commit_group;" ::: "memory")
#define CP_WAIT0()  asm volatile("cp.async.wait_group 0;" ::: "memory")

// bf16 split helpers
__device__ __forceinline__ uint32_t pk(float a, float b) {
    uint32_t ua = (uint32_t)__bfloat16_as_ushort(__float2bfloat16(a));
    uint32_t ub = (uint32_t)__bfloat16_as_ushort(__float2bfloat16(b));
    return ua | (ub << 16);
}
__device__ __forceinline__ float resid(float v) {
    return v - __bfloat162float(__float2bfloat16(v));
}
__device__ __forceinline__ void split2(float a, float b,
                                       uint32_t& hi, uint32_t& lo) {
    __nv_bfloat16 ha = __float2bfloat16(a), hb = __float2bfloat16(b);
    hi = (uint32_t)__bfloat16_as_ushort(ha) |
         ((uint32_t)__bfloat16_as_ushort(hb) << 16);
    lo = pk(a - __bfloat162float(ha), b - __bfloat162float(hb));
}

// ---------------------------------------------------------------------------
// Projection: out = w[CI,C] @ x[b][C,N] + bias -> split to bf16 hi/lo
//   transOut=1 -> out[b][n][ci] ; transOut=0 -> out[b][ci][n]
// ---------------------------------------------------------------------------
__global__ __launch_bounds__(256)
void proj_kernel(const float* __restrict__ x, const float* __restrict__ w,
                 const float* __restrict__ bias,
                 __nv_bfloat16* __restrict__ outHi,
                 __nv_bfloat16* __restrict__ outLo, int transOut) {
    __shared__ float sX[32][64];
    __shared__ float sW[128][32];

    const int bb = blockIdx.y;
    const int n0 = blockIdx.x * 64;
    const int t  = threadIdx.x;
    const int tx = t & 15, ty = t >> 4;

    float acc[8][4];
#pragma unroll
    for (int i = 0; i < 8; i++)
#pragma unroll
        for (int j = 0; j < 4; j++) acc[i][j] = 0.f;

    const float* xb = x + (size_t)bb * C_IN * NPIX;

    for (int c0 = 0; c0 < C_IN; c0 += 32) {
#pragma unroll
        for (int i = 0; i < 8; i++) {
            int idx = t + i * 256;
            int c = idx >> 6, n = idx & 63;
            sX[c][n] = xb[(size_t)(c0 + c) * NPIX + n0 + n];
        }
#pragma unroll
        for (int i = 0; i < 16; i++) {
            int idx = t + i * 256;
            int ci = idx >> 5, c = idx & 31;
            sW[ci][c] = w[ci * C_IN + c0 + c];
        }
        __syncthreads();

#pragma unroll 8
        for (int k = 0; k < 32; k++) {
            float wf[8];
#pragma unroll
            for (int i = 0; i < 8; i++) wf[i] = sW[8 * ty + i][k];
            float4 xv = *(const float4*)&sX[k][4 * tx];
            float xf[4] = {xv.x, xv.y, xv.z, xv.w};
#pragma unroll
            for (int i = 0; i < 8; i++)
#pragma unroll
                for (int j = 0; j < 4; j++) acc[i][j] += wf[i] * xf[j];
        }
        __syncthreads();
    }

    float bv[8];
#pragma unroll
    for (int i = 0; i < 8; i++) bv[i] = bias[8 * ty + i];

    if (transOut) {
#pragma unroll
        for (int j = 0; j < 4; j++) {
            int n = n0 + 4 * tx + j;
            float v[8];
#pragma unroll
            for (int i = 0; i < 8; i++) v[i] = acc[i][j] + bv[i];
            size_t o = ((size_t)bb * NPIX + n) * CI + 8 * ty;
            uint4 H, L;
            H.x = pk(v[0], v[1]); H.y = pk(v[2], v[3]);
            H.z = pk(v[4], v[5]); H.w = pk(v[6], v[7]);
            L.x = pk(resid(v[0]), resid(v[1])); L.y = pk(resid(v[2]), resid(v[3]));
            L.z = pk(resid(v[4]), resid(v[5])); L.w = pk(resid(v[6]), resid(v[7]));
            *(uint4*)(outHi + o) = H;
            *(uint4*)(outLo + o) = L;
        }
    } else {
#pragma unroll
        for (int i = 0; i < 8; i++) {
            int ci = 8 * ty + i;
            float v[4];
#pragma unroll
            for (int j = 0; j < 4; j++) v[j] = acc[i][j] + bv[i];
            size_t o = ((size_t)bb * CI + ci) * NPIX + n0 + 4 * tx;
            uint2 H, L;
            H.x = pk(v[0], v[1]); H.y = pk(v[2], v[3]);
            L.x = pk(resid(v[0]), resid(v[1])); L.y = pk(resid(v[2]), resid(v[3]));
            *(uint2*)(outHi + o) = H;
            *(uint2*)(outLo + o) = L;
        }
    }
}

// ---------------------------------------------------------------------------
// attn (warp HMMA): Y[b][n][ci] = sum_m (T[n][:].Phi[m][:]/N) * G[:, m]
// split-bf16: hi*hi + hi*lo + lo*hi, fp32 accumulate.
// ---------------------------------------------------------------------------
// SMEM layout (bytes). Row pitches: T/Phi 272 (=136 bf16), G 144 (=72 bf16).
#define T_PITCH   272u
#define G_PITCH   144u
#define OFF_THI   0u
#define OFF_TLO   34816u                 // 128*272
#define OFF_PH    69632u                 // per buf 34816 (hi at +0, lo at +17408)
#define PH_BUFSZ  34816u
#define PH_LO     17408u                 // 64*272
#define OFF_G     139264u                // per buf 36864 (hi at +0, lo at +18432)
#define G_BUFSZ   36864u
#define G_LO      18432u                 // 128*144
#define SMEM_BYTES 212992u

__device__ __forceinline__ void load_chunk(uint32_t sb, int buf, int bb, int m0,
                                           int tid,
                                           const __nv_bfloat16* Phh,
                                           const __nv_bfloat16* Phl,
                                           const __nv_bfloat16* Ghi,
                                           const __nv_bfloat16* Glo) {
    const uint32_t phiB = sb + OFF_PH + (uint32_t)buf * PH_BUFSZ;
    const uint32_t gB   = sb + OFF_G  + (uint32_t)buf * G_BUFSZ;
    // Phi chunk [64 m][128 ci] hi+lo : 1024 granules each
#pragma unroll
    for (int i = 0; i < 4; i++) {
        int idx = tid + i * 256;
        int r = idx >> 4, c8 = idx & 15;
        size_t so = ((size_t)(bb * NPIX + m0 + r)) * CI + c8 * 8;
        uint32_t d = phiB + (uint32_t)r * T_PITCH + (uint32_t)c8 * 16u;
        CP16(d,          Phh + so);
        CP16(d + PH_LO,  Phl + so);
    }
    // G chunk [128 ci][64 m] hi+lo : 1024 granules each
#pragma unroll
    for (int i = 0; i < 4; i++) {
        int idx = tid + i * 256;
        int ci = idx >> 3, m8 = idx & 7;
        size_t so = ((size_t)(bb * CI + ci)) * NPIX + m0 + m8 * 8;
        uint32_t d = gB + (uint32_t)ci * G_PITCH + (uint32_t)m8 * 16u;
        CP16(d,         Ghi + so);
        CP16(d + G_LO,  Glo + so);
    }
}

__global__ __launch_bounds__(256, 1)
void attn_hmma_kernel(const __nv_bfloat16* __restrict__ Thi,
                      const __nv_bfloat16* __restrict__ Tlo,
                      const __nv_bfloat16* __restrict__ Phh,
                      const __nv_bfloat16* __restrict__ Phl,
                      const __nv_bfloat16* __restrict__ Ghi,
                      const __nv_bfloat16* __restrict__ Glo,
                      float* __restrict__ Y) {
    extern __shared__ char smem[];
    const uint32_t sb = smem_u32(smem);
    const int tid  = threadIdx.x;
    const int wid  = tid >> 5;
    const int lane = tid & 31;
    const int bb   = blockIdx.y;
    const int n0   = blockIdx.x * NT;
    const int n0c  = wid * 16;          // warp's 16 rows within the CTA tile

    // ldmatrix per-lane address components
    const int lm  = lane & 7;
    const int mid = lane >> 3;
    const int arow = (mid & 1) * 8 + lm;        // A-style: M0/M2 rows 0-7
    const int acol = (mid >> 1) * 16;           //          M2/M3 +8 cols
    const int brow = (mid >> 1) * 8 + lm;       // B-style: M2/M3 rows +8
    const int bcol = (mid & 1) * 16;            //          M1/M3 +8 cols

    // ---- prologue: T tile (hi+lo) + chunk 0
#pragma unroll
    for (int i = 0; i < 8; i++) {
        int idx = tid + i * 256;
        int r = idx >> 4, c8 = idx & 15;
        size_t so = ((size_t)(bb * NPIX + n0 + r)) * CI + c8 * 8;
        uint32_t d = sb + OFF_THI + (uint32_t)r * T_PITCH + (uint32_t)c8 * 16u;
        CP16(d,                       Thi + so);
        CP16(d + (OFF_TLO - OFF_THI), Tlo + so);
    }
    load_chunk(sb, 0, bb, 0, tid, Phh, Phl, Ghi, Glo);
    CP_COMMIT();
    CP_WAIT0();
    __syncthreads();

    float yacc[16][4];
#pragma unroll
    for (int t = 0; t < 16; t++)
#pragma unroll
        for (int j = 0; j < 4; j++) yacc[t][j] = 0.f;

    const float invN = 1.0f / (float)NPIX;
    const uint32_t aHiBase = sb + OFF_THI +
        (uint32_t)(n0c + arow) * T_PITCH + (uint32_t)acol;

    for (int it = 0; it < NCHUNK; it++) {
        const int buf = it & 1;
        if (it + 1 < NCHUNK) {
            load_chunk(sb, buf ^ 1, bb, (it + 1) * MT, tid, Phh, Phl, Ghi, Glo);
            CP_COMMIT();
        }

        // ---- MMA1: S[16 n][64 m] = T . Phi^T  (K = 128 ci)
        float sacc[8][4];
#pragma unroll
        for (int j = 0; j < 8; j++)
#pragma unroll
            for (int q = 0; q < 4; q++) sacc[j][q] = 0.f;

        const uint32_t phiB = sb + OFF_PH + (uint32_t)buf * PH_BUFSZ +
                              (uint32_t)brow * T_PITCH + (uint32_t)bcol;
#pragma unroll
        for (int kk = 0; kk < 8; kk++) {
            uint32_t ah[4], al[4];
            LDM_X4(ah, aHiBase + 32u * kk);
            LDM_X4(al, aHiBase + (OFF_TLO - OFF_THI) + 32u * kk);
#pragma unroll
            for (int p = 0; p < 4; p++) {
                uint32_t bh[4], bl[4];
                uint32_t ba = phiB + (uint32_t)(16 * p) * T_PITCH + 32u * kk;
                LDM_X4(bh, ba);
                LDM_X4(bl, ba + PH_LO);
                mma16816(sacc[2 * p],     ah, bh[0], bh[1]);
                mma16816(sacc[2 * p],     ah, bl[0], bl[1]);
                mma16816(sacc[2 * p],     al, bh[0], bh[1]);
                mma16816(sacc[2 * p + 1], ah, bh[2], bh[3]);
                mma16816(sacc[2 * p + 1], ah, bl[2], bl[3]);
                mma16816(sacc[2 * p + 1], al, bh[2], bh[3]);
            }
        }

        // ---- MMA2: Y[16 n][128 ci] += (S/N) . G   (K = 64 m)
        // mma accumulator layout == A-fragment layout: repack in registers.
        const uint32_t gB = sb + OFF_G + (uint32_t)buf * G_BUFSZ +
                            (uint32_t)brow * G_PITCH + (uint32_t)bcol;
#pragma unroll
        for (int kk = 0; kk < 4; kk++) {
            uint32_t Ah[4], Al[4];
            split2(sacc[2 * kk][0] * invN,     sacc[2 * kk][1] * invN,     Ah[0], Al[0]);
            split2(sacc[2 * kk][2] * invN,     sacc[2 * kk][3] * invN,     Ah[1], Al[1]);
            split2(sacc[2 * kk + 1][0] * invN, sacc[2 * kk + 1][1] * invN, Ah[2], Al[2]);
            split2(sacc[2 * kk + 1][2] * invN, sacc[2 * kk + 1][3] * invN, Ah[3], Al[3]);
#pragma unroll
            for (int cp = 0; cp < 8; cp++) {
                uint32_t bh[4], bl[4];
                uint32_t ga = gB + (uint32_t)(16 * cp) * G_PITCH + 32u * kk;
                LDM_X4(bh, ga);
                LDM_X4(bl, ga + G_LO);
                mma16816(yacc[2 * cp],     Ah, bh[0], bh[1]);
                mma16816(yacc[2 * cp],     Ah, bl[0], bl[1]);
                mma16816(yacc[2 * cp],     Al, bh[0], bh[1]);
                mma16816(yacc[2 * cp + 1], Ah, bh[2], bh[3]);
                mma16816(yacc[2 * cp + 1], Ah, bl[2], bl[3]);
                mma16816(yacc[2 * cp + 1], Al, bh[2], bh[3]);
            }
        }

        if (it + 1 < NCHUNK) CP_WAIT0();
        __syncthreads();
    }

    // ---- store Y[b][n][ci] (fp32)
    const int gq = lane >> 2, tig = lane & 3;
    float* Yrow = Y + ((size_t)bb * NPIX + n0 + n0c + gq) * CI + 2 * tig;
#pragma unroll
    for (int t = 0; t < 16; t++) {
        *(float2*)(Yrow + 8 * t)          = make_float2(yacc[t][0], yacc[t][1]);
        *(float2*)(Yrow + 8 * t + 8 * CI) = make_float2(yacc[t][2], yacc[t][3]);
    }
}

// ---------------------------------------------------------------------------
// Final: out[b][c][n] = A[c] * (W_w[c,:] . Y[b][n][:]) + Bb[c]
// ---------------------------------------------------------------------------
__global__ __launch_bounds__(256)
void final_kernel(const float* __restrict__ Y, const float* __restrict__ Ww,
                  const float* __restrict__ gamma, const float* __restrict__ beta,
                  const float* __restrict__ mean, const float* __restrict__ var,
                  float* __restrict__ out) {
    __shared__ float sY[64][129];
    __shared__ float sW[64][128];

    const int bb = blockIdx.z;
    const int c0 = blockIdx.y * 64;
    const int n0 = blockIdx.x * 64;
    const int t  = threadIdx.x;
    const int tx = t & 15, ty = t >> 4;

#pragma unroll
    for (int i = 0; i < 8; i++) {
        int idx = t + i * 256;
        int r = idx >> 5, c4 = idx & 31;
        *(float4*)&sW[r][4 * c4] = *(const float4*)&Ww[(c0 + r) * CI + 4 * c4];
    }
    const float* Yb = Y + ((size_t)bb * NPIX + n0) * CI;
#pragma unroll
    for (int i = 0; i < 32; i++) {
        int idx = t + i * 256;
        int n = idx >> 7, k = idx & 127;
        sY[n][k] = Yb[(size_t)n * CI + k];
    }
    __syncthreads();

    float acc[4][4];
#pragma unroll
    for (int i = 0; i < 4; i++)
#pragma unroll
        for (int j = 0; j < 4; j++) acc[i][j] = 0.f;

#pragma unroll 4
    for (int k = 0; k < 128; k++) {
        float wf[4], yf[4];
#pragma unroll
        for (int i = 0; i < 4; i++) wf[i] = sW[4 * ty + i][k];
#pragma unroll
        for (int j = 0; j < 4; j++) yf[j] = sY[4 * tx + j][k];
#pragma unroll
        for (int i = 0; i < 4; i++)
#pragma unroll
            for (int j = 0; j < 4; j++) acc[i][j] += wf[i] * yf[j];
    }

#pragma unroll
    for (int i = 0; i < 4; i++) {
        int c = c0 + 4 * ty + i;
        float inv = rsqrtf(var[c] + 1e-5f);
        float A  = gamma[c] * inv;
        float Bb = beta[c] - mean[c] * A;
        float* o = out + ((size_t)bb * C_IN + c) * NPIX + n0 + 4 * tx;
        *(float4*)o = make_float4(acc[i][0] * A + Bb, acc[i][1] * A + Bb,
                                  acc[i][2] * A + Bb, acc[i][3] * A + Bb);
    }
}

// ---------------------------------------------------------------------------
// Launch
// ---------------------------------------------------------------------------
extern "C" void kernel_launch(void* const* d_in, const int* in_sizes, int n_in,
                              void* d_out, int out_size) {
    const float* a       = (const float*)d_in[0];
    const float* b       = (const float*)d_in[1];
    const float* theta_w = (const float*)d_in[2];
    const float* theta_b = (const float*)d_in[3];
    const float* phi_w   = (const float*)d_in[4];
    const float* phi_b   = (const float*)d_in[5];
    const float* g_w     = (const float*)d_in[6];
    const float* g_b     = (const float*)d_in[7];
    const float* W_w     = (const float*)d_in[8];
    const float* bn_g    = (const float*)d_in[9];
    const float* bn_be   = (const float*)d_in[10];
    const float* bn_m    = (const float*)d_in[11];
    const float* bn_v    = (const float*)d_in[12];
    float* out = (float*)d_out;

    __nv_bfloat16 *Thi, *Tlo, *Phh, *Phl, *Ghi, *Glo;
    float* Y;
    cudaGetSymbolAddress((void**)&Thi, g_Thi);
    cudaGetSymbolAddress((void**)&Tlo, g_Tlo);
    cudaGetSymbolAddress((void**)&Phh, g_Phh);
    cudaGetSymbolAddress((void**)&Phl, g_Phl);
    cudaGetSymbolAddress((void**)&Ghi, g_Ghi);
    cudaGetSymbolAddress((void**)&Glo, g_Glo);
    cudaGetSymbolAddress((void**)&Y,   g_Y);

    dim3 projGrid(NPIX / 64, BATCH);
    proj_kernel<<<projGrid, 256>>>(a, theta_w, theta_b, Thi, Tlo, 1);
    proj_kernel<<<projGrid, 256>>>(b, phi_w,   phi_b,   Phh, Phl, 1);
    proj_kernel<<<projGrid, 256>>>(b, g_w,     g_b,     Ghi, Glo, 0);

    cudaFuncSetAttribute(attn_hmma_kernel,
                         cudaFuncAttributeMaxDynamicSharedMemorySize, SMEM_BYTES);
    dim3 attnGrid(NPIX / NT, BATCH);
    attn_hmma_kernel<<<attnGrid, 256, SMEM_BYTES>>>(Thi, Tlo, Phh, Phl,
                                                    Ghi, Glo, Y);

    dim3 finGrid(NPIX / 64, C_IN / 64, BATCH);
    final_kernel<<<finGrid, 256>>>(Y, W_w, bn_g, bn_be, bn_m, bn_v, out);
}

// round 8
// speedup vs baseline: 3.5618x; 1.1317x over previous
#include <cuda_runtime.h>
#include <cuda_bf16.h>
#include <cstdint>
#include <cstddef>

// Problem constants
#define BATCH 4
#define C_IN  256
#define CI    128
#define NPIX  4096   // 64*64
#define NT    128    // n-rows per attn CTA
#define MT    64     // m-chunk
#define NCHUNK (NPIX / MT)   // 64

// ---------------------------------------------------------------------------
// Scratch (allocation-free: __device__ globals)
// ---------------------------------------------------------------------------
__device__ __nv_bfloat16 g_Thi[(size_t)BATCH * NPIX * CI];  // theta(a) [B][n][ci]
__device__ __nv_bfloat16 g_Tlo[(size_t)BATCH * NPIX * CI];
__device__ __nv_bfloat16 g_Phh[(size_t)BATCH * NPIX * CI];  // phi(b)   [B][m][ci]
__device__ __nv_bfloat16 g_Phl[(size_t)BATCH * NPIX * CI];
__device__ __nv_bfloat16 g_Ghi[(size_t)BATCH * CI * NPIX];  // g(b)     [B][ci][m]
__device__ __nv_bfloat16 g_Glo[(size_t)BATCH * CI * NPIX];
__device__ __nv_bfloat16 g_Yhi[(size_t)BATCH * NPIX * CI];  // y        [B][n][ci]
__device__ __nv_bfloat16 g_Ylo[(size_t)BATCH * NPIX * CI];

// ---------------------------------------------------------------------------
// PTX helpers (baseline features only: valid under compute_103)
// ---------------------------------------------------------------------------
__device__ __forceinline__ uint32_t smem_u32(const void* p) {
    uint32_t a;
    asm("{ .reg .u64 t; cvta.to.shared.u64 t, %1; cvt.u32.u64 %0, t; }"
        : "=r"(a) : "l"(p));
    return a;
}

#define LDM_X4(r, a)                                                          \
    asm volatile("ldmatrix.sync.aligned.m8n8.x4.shared.b16 {%0,%1,%2,%3}, [%4];" \
        : "=r"((r)[0]), "=r"((r)[1]), "=r"((r)[2]), "=r"((r)[3]) : "r"(a))

// NOTE: non-volatile, no memory clobber: pure register op -> ptxas may schedule.
__device__ __forceinline__ void mma16816(float* d, const uint32_t* a,
                                         uint32_t b0, uint32_t b1) {
    asm("mma.sync.aligned.m16n8k16.row.col.f32.bf16.bf16.f32 "
        "{%0,%1,%2,%3}, {%4,%5,%6,%7}, {%8,%9}, {%0,%1,%2,%3};"
        : "+f"(d[0]), "+f"(d[1]), "+f"(d[2]), "+f"(d[3])
        : "r"(a[0]), "r"(a[1]), "r"(a[2]), "r"(a[3]), "r"(b0), "r"(b1));
}

#define CP16(dst, src)                                                        \
    asm volatile("cp.async.cg.shared.global [%0], [%1], 16;"                  \
                 :: "r"(dst), "l"(src) : "memory")
#define CP_COMMIT() asm volatile("cp.async.commit_group;" ::: "memory")
#define CP_WAIT0()  asm volatile("cp.async.wait_group 0;" ::: "memory")

// bf16 split helpers
__device__ __forceinline__ uint32_t pk(float a, float b) {
    uint32_t ua = (uint32_t)__bfloat16_as_ushort(__float2bfloat16(a));
    uint32_t ub = (uint32_t)__bfloat16_as_ushort(__float2bfloat16(b));
    return ua | (ub << 16);
}
__device__ __forceinline__ float resid(float v) {
    return v - __bfloat162float(__float2bfloat16(v));
}
__device__ __forceinline__ void split2(float a, float b,
                                       uint32_t& hi, uint32_t& lo) {
    __nv_bfloat16 ha = __float2bfloat16(a), hb = __float2bfloat16(b);
    hi = (uint32_t)__bfloat16_as_ushort(ha) |
         ((uint32_t)__bfloat16_as_ushort(hb) << 16);
    lo = pk(a - __bfloat162float(ha), b - __bfloat162float(hb));
}

// emit the 6 split-bf16 MMAs for one n16 B panel, interleaved accumulators
__device__ __forceinline__ void mma6(float* d0, float* d1,
                                     const uint32_t* ah, const uint32_t* al,
                                     const uint32_t* bh, const uint32_t* bl) {
    mma16816(d0, ah, bh[0], bh[1]);
    mma16816(d1, ah, bh[2], bh[3]);
    mma16816(d0, ah, bl[0], bl[1]);
    mma16816(d1, ah, bl[2], bl[3]);
    mma16816(d0, al, bh[0], bh[1]);
    mma16816(d1, al, bh[2], bh[3]);
}

// ---------------------------------------------------------------------------
// proj (HMMA): out = w[CI,C] @ x[b][C,:] + bias, split-bf16 emulation.
// TRANS=1 -> out[b][n][ci] (theta/phi) ; TRANS=0 -> out[b][ci][n] (g)
// CTA: 64-n tile x batch. K = C = 256.
// smem: xT [64 n][256 c] hi/lo + w [128 ci][256 c] hi/lo, pitch 528B.
// ---------------------------------------------------------------------------
#define PJ_PITCH 528u
#define PJ_XH 0u
#define PJ_XL 33792u
#define PJ_WH 67584u
#define PJ_WL 135168u
#define PJ_SMEM 202752u

template<int TRANS>
__global__ __launch_bounds__(256)
void proj_mma_kernel(const float* __restrict__ x, const float* __restrict__ w,
                     const float* __restrict__ bias,
                     __nv_bfloat16* __restrict__ outHi,
                     __nv_bfloat16* __restrict__ outLo) {
    extern __shared__ char psm[];
    const uint32_t sb = smem_u32(psm);
    const int tid = threadIdx.x, lane = tid & 31, wid = tid >> 5;
    const int bb = blockIdx.y, n0 = blockIdx.x * 64;

    // ---- stage x^T tile: [64 n][256 c] hi/lo (transpose during store)
#pragma unroll
    for (int i = 0; i < 16; i++) {
        int idx = tid + i * 256;
        int c = idx >> 4, n4 = idx & 15;
        float4 v = *(const float4*)&x[((size_t)bb * C_IN + c) * NPIX + n0 + 4 * n4];
        float vv[4] = {v.x, v.y, v.z, v.w};
#pragma unroll
        for (int j = 0; j < 4; j++) {
            __nv_bfloat16 h = __float2bfloat16(vv[j]);
            uint32_t o = (uint32_t)(4 * n4 + j) * PJ_PITCH + 2u * (uint32_t)c;
            *(unsigned short*)(psm + PJ_XH + o) = __bfloat16_as_ushort(h);
            *(unsigned short*)(psm + PJ_XL + o) =
                __bfloat16_as_ushort(__float2bfloat16(vv[j] - __bfloat162float(h)));
        }
    }
    // ---- stage w: [128 ci][256 c] hi/lo
#pragma unroll
    for (int i = 0; i < 32; i++) {
        int idx = tid + i * 256;
        int r = idx >> 6, c4 = idx & 63;
        float4 v = *(const float4*)&w[(size_t)r * C_IN + 4 * c4];
        uint2 H, L;
        H.x = pk(v.x, v.y); H.y = pk(v.z, v.w);
        L.x = pk(resid(v.x), resid(v.y)); L.y = pk(resid(v.z), resid(v.w));
        uint32_t o = (uint32_t)r * PJ_PITCH + 8u * (uint32_t)c4;
        *(uint2*)(psm + PJ_WH + o) = H;
        *(uint2*)(psm + PJ_WL + o) = L;
    }
    __syncthreads();

    const int lm = lane & 7, mid = lane >> 3;
    const int arow = (mid & 1) * 8 + lm, acolB = (mid >> 1) * 16;
    const int brow = (mid >> 1) * 8 + lm, bcolB = (mid & 1) * 16;

    uint32_t aBase, bBase, aLd, bLd;
    if (TRANS) {   // A = xT (M=64 n), B = w (N=128 ci, warp gets 64)
        int mi = wid & 3, ch = wid >> 2;
        aBase = sb + PJ_XH + (uint32_t)(mi * 16 + arow) * PJ_PITCH + acolB;
        bBase = sb + PJ_WH + (uint32_t)(ch * 64 + brow) * PJ_PITCH + bcolB;
        aLd = PJ_XL - PJ_XH; bLd = PJ_WL - PJ_WH;
    } else {       // A = w (M=128 ci), B = xT (N=64 n)
        aBase = sb + PJ_WH + (uint32_t)(wid * 16 + arow) * PJ_PITCH + acolB;
        bBase = sb + PJ_XH + (uint32_t)brow * PJ_PITCH + bcolB;
        aLd = PJ_WL - PJ_WH; bLd = PJ_XL - PJ_XH;
    }

    float acc[8][4];
#pragma unroll
    for (int j = 0; j < 8; j++)
#pragma unroll
        for (int q = 0; q < 4; q++) acc[j][q] = 0.f;

#pragma unroll 4
    for (int kk = 0; kk < 16; kk++) {
        uint32_t ah[4], al[4];
        LDM_X4(ah, aBase + 32u * kk);
        LDM_X4(al, aBase + aLd + 32u * kk);
#pragma unroll
        for (int p = 0; p < 4; p++) {
            uint32_t bh[4], bl[4];
            uint32_t ba = bBase + (uint32_t)(16 * p) * PJ_PITCH + 32u * kk;
            LDM_X4(bh, ba);
            LDM_X4(bl, ba + bLd);
            mma6(acc[2 * p], acc[2 * p + 1], ah, al, bh, bl);
        }
    }

    // ---- epilogue: +bias, split hi/lo, store
    const int gq = lane >> 2, tig = lane & 3;
    if (TRANS) {
        int mi = wid & 3, ch = wid >> 2;
        int nA = n0 + mi * 16 + gq;
#pragma unroll
        for (int j = 0; j < 8; j++) {
            int ci = ch * 64 + j * 8 + 2 * tig;
            float b0 = bias[ci], b1 = bias[ci + 1];
            uint32_t h, l;
            size_t o = ((size_t)bb * NPIX + nA) * CI + ci;
            split2(acc[j][0] + b0, acc[j][1] + b1, h, l);
            *(uint32_t*)(outHi + o) = h; *(uint32_t*)(outLo + o) = l;
            split2(acc[j][2] + b0, acc[j][3] + b1, h, l);
            o += (size_t)8 * CI;
            *(uint32_t*)(outHi + o) = h; *(uint32_t*)(outLo + o) = l;
        }
    } else {
        int ciA = wid * 16 + gq;
        float b0 = bias[ciA], b1 = bias[ciA + 8];
#pragma unroll
        for (int j = 0; j < 8; j++) {
            int n = n0 + j * 8 + 2 * tig;
            uint32_t h, l;
            size_t o = ((size_t)bb * CI + ciA) * NPIX + n;
            split2(acc[j][0] + b0, acc[j][1] + b0, h, l);
            *(uint32_t*)(outHi + o) = h; *(uint32_t*)(outLo + o) = l;
            split2(acc[j][2] + b1, acc[j][3] + b1, h, l);
            o += (size_t)8 * NPIX;
            *(uint32_t*)(outHi + o) = h; *(uint32_t*)(outLo + o) = l;
        }
    }
}

// ---------------------------------------------------------------------------
// attn (warp HMMA): Y[b][n][ci] = sum_m (T[n][:].Phi[m][:]/N) * G[:, m]
// split-bf16: hi*hi + hi*lo + lo*hi, fp32 accumulate. Y out as bf16 hi/lo.
// ---------------------------------------------------------------------------
#define T_PITCH   272u
#define G_PITCH   144u
#define OFF_THI   0u
#define OFF_TLO   34816u
#define OFF_PH    69632u
#define PH_BUFSZ  34816u
#define PH_LO     17408u
#define OFF_G     139264u
#define G_BUFSZ   36864u
#define G_LO      18432u
#define SMEM_BYTES 212992u

__device__ __forceinline__ void load_chunk(uint32_t sb, int buf, int bb, int m0,
                                           int tid,
                                           const __nv_bfloat16* Phh,
                                           const __nv_bfloat16* Phl,
                                           const __nv_bfloat16* Ghi,
                                           const __nv_bfloat16* Glo) {
    const uint32_t phiB = sb + OFF_PH + (uint32_t)buf * PH_BUFSZ;
    const uint32_t gB   = sb + OFF_G  + (uint32_t)buf * G_BUFSZ;
#pragma unroll
    for (int i = 0; i < 4; i++) {
        int idx = tid + i * 256;
        int r = idx >> 4, c8 = idx & 15;
        size_t so = ((size_t)(bb * NPIX + m0 + r)) * CI + c8 * 8;
        uint32_t d = phiB + (uint32_t)r * T_PITCH + (uint32_t)c8 * 16u;
        CP16(d,          Phh + so);
        CP16(d + PH_LO,  Phl + so);
    }
#pragma unroll
    for (int i = 0; i < 4; i++) {
        int idx = tid + i * 256;
        int ci = idx >> 3, m8 = idx & 7;
        size_t so = ((size_t)(bb * CI + ci)) * NPIX + m0 + m8 * 8;
        uint32_t d = gB + (uint32_t)ci * G_PITCH + (uint32_t)m8 * 16u;
        CP16(d,         Ghi + so);
        CP16(d + G_LO,  Glo + so);
    }
}

__global__ __launch_bounds__(256, 1)
void attn_hmma_kernel(const __nv_bfloat16* __restrict__ Thi,
                      const __nv_bfloat16* __restrict__ Tlo,
                      const __nv_bfloat16* __restrict__ Phh,
                      const __nv_bfloat16* __restrict__ Phl,
                      const __nv_bfloat16* __restrict__ Ghi,
                      const __nv_bfloat16* __restrict__ Glo,
                      __nv_bfloat16* __restrict__ Yhi,
                      __nv_bfloat16* __restrict__ Ylo) {
    extern __shared__ char smem[];
    const uint32_t sb = smem_u32(smem);
    const int tid  = threadIdx.x;
    const int wid  = tid >> 5;
    const int lane = tid & 31;
    const int bb   = blockIdx.y;
    const int n0   = blockIdx.x * NT;
    const int n0c  = wid * 16;

    const int lm  = lane & 7;
    const int mid = lane >> 3;
    const int arow = (mid & 1) * 8 + lm;
    const int acol = (mid >> 1) * 16;
    const int brow = (mid >> 1) * 8 + lm;
    const int bcol = (mid & 1) * 16;

    // ---- prologue: T tile (hi+lo) + chunk 0
#pragma unroll
    for (int i = 0; i < 8; i++) {
        int idx = tid + i * 256;
        int r = idx >> 4, c8 = idx & 15;
        size_t so = ((size_t)(bb * NPIX + n0 + r)) * CI + c8 * 8;
        uint32_t d = sb + OFF_THI + (uint32_t)r * T_PITCH + (uint32_t)c8 * 16u;
        CP16(d,                       Thi + so);
        CP16(d + (OFF_TLO - OFF_THI), Tlo + so);
    }
    load_chunk(sb, 0, bb, 0, tid, Phh, Phl, Ghi, Glo);
    CP_COMMIT();
    CP_WAIT0();
    __syncthreads();

    float yacc[16][4];
#pragma unroll
    for (int t = 0; t < 16; t++)
#pragma unroll
        for (int j = 0; j < 4; j++) yacc[t][j] = 0.f;

    const float invN = 1.0f / (float)NPIX;
    const uint32_t aHiBase = sb + OFF_THI +
        (uint32_t)(n0c + arow) * T_PITCH + (uint32_t)acol;

    for (int it = 0; it < NCHUNK; it++) {
        const int buf = it & 1;
        if (it + 1 < NCHUNK) {
            load_chunk(sb, buf ^ 1, bb, (it + 1) * MT, tid, Phh, Phl, Ghi, Glo);
            CP_COMMIT();
        }

        // ---- MMA1: S[16 n][64 m] = T . Phi^T  (K = 128 ci)
        float sacc[8][4];
#pragma unroll
        for (int j = 0; j < 8; j++)
#pragma unroll
            for (int q = 0; q < 4; q++) sacc[j][q] = 0.f;

        const uint32_t phiB = sb + OFF_PH + (uint32_t)buf * PH_BUFSZ +
                              (uint32_t)brow * T_PITCH + (uint32_t)bcol;
#pragma unroll
        for (int kk = 0; kk < 8; kk++) {
            uint32_t ah[4], al[4];
            LDM_X4(ah, aHiBase + 32u * kk);
            LDM_X4(al, aHiBase + (OFF_TLO - OFF_THI) + 32u * kk);
#pragma unroll
            for (int p = 0; p < 4; p++) {
                uint32_t bh[4], bl[4];
                uint32_t ba = phiB + (uint32_t)(16 * p) * T_PITCH + 32u * kk;
                LDM_X4(bh, ba);
                LDM_X4(bl, ba + PH_LO);
                mma6(sacc[2 * p], sacc[2 * p + 1], ah, al, bh, bl);
            }
        }

        // ---- MMA2: Y[16 n][128 ci] += (S/N) . G   (K = 64 m)
        const uint32_t gB = sb + OFF_G + (uint32_t)buf * G_BUFSZ +
                            (uint32_t)brow * G_PITCH + (uint32_t)bcol;
#pragma unroll
        for (int kk = 0; kk < 4; kk++) {
            uint32_t Ah[4], Al[4];
            split2(sacc[2 * kk][0] * invN,     sacc[2 * kk][1] * invN,     Ah[0], Al[0]);
            split2(sacc[2 * kk][2] * invN,     sacc[2 * kk][3] * invN,     Ah[1], Al[1]);
            split2(sacc[2 * kk + 1][0] * invN, sacc[2 * kk + 1][1] * invN, Ah[2], Al[2]);
            split2(sacc[2 * kk + 1][2] * invN, sacc[2 * kk + 1][3] * invN, Ah[3], Al[3]);
#pragma unroll
            for (int cp = 0; cp < 8; cp++) {
                uint32_t bh[4], bl[4];
                uint32_t ga = gB + (uint32_t)(16 * cp) * G_PITCH + 32u * kk;
                LDM_X4(bh, ga);
                LDM_X4(bl, ga + G_LO);
                mma6(yacc[2 * cp], yacc[2 * cp + 1], Ah, Al, bh, bl);
            }
        }

        if (it + 1 < NCHUNK) CP_WAIT0();
        __syncthreads();
    }

    // ---- store Y[b][n][ci] as bf16 hi/lo
    const int gq = lane >> 2, tig = lane & 3;
    const size_t yb = ((size_t)bb * NPIX + n0 + n0c + gq) * CI + 2 * tig;
#pragma unroll
    for (int t = 0; t < 16; t++) {
        uint32_t h, l;
        size_t o = yb + 8 * t;
        split2(yacc[t][0], yacc[t][1], h, l);
        *(uint32_t*)(Yhi + o) = h; *(uint32_t*)(Ylo + o) = l;
        split2(yacc[t][2], yacc[t][3], h, l);
        o += (size_t)8 * CI;
        *(uint32_t*)(Yhi + o) = h; *(uint32_t*)(Ylo + o) = l;
    }
}

// ---------------------------------------------------------------------------
// final (HMMA): out[b][c][n] = A[c]*(W_w[c,:] . Y[n,:]) + Bb[c]
// CTA tile: [128 c][128 n], K=128 (ci). smem pitch 272B.
// ---------------------------------------------------------------------------
#define FN_PITCH 272u
#define FN_WH 0u
#define FN_WL 34816u
#define FN_YH 69632u
#define FN_YL 104448u
#define FN_SMEM 139264u

__global__ __launch_bounds__(256)
void final_mma_kernel(const __nv_bfloat16* __restrict__ Yhi,
                      const __nv_bfloat16* __restrict__ Ylo,
                      const float* __restrict__ Ww,
                      const float* __restrict__ gamma,
                      const float* __restrict__ beta,
                      const float* __restrict__ mean,
                      const float* __restrict__ var,
                      float* __restrict__ out) {
    extern __shared__ char fsm[];
    const uint32_t sb = smem_u32(fsm);
    const int tid = threadIdx.x, lane = tid & 31, wid = tid >> 5;
    const int bb = blockIdx.z;
    const int c0 = blockIdx.y * 128;
    const int n0 = blockIdx.x * 128;

    // ---- stage Y hi/lo via cp.async: [128 n][128 ci]
#pragma unroll
    for (int i = 0; i < 8; i++) {
        int idx = tid + i * 256;
        int r = idx >> 4, g = idx & 15;
        size_t so = ((size_t)bb * NPIX + n0 + r) * CI + 8 * g;
        uint32_t d = sb + FN_YH + (uint32_t)r * FN_PITCH + 16u * (uint32_t)g;
        CP16(d, Yhi + so);
        CP16(d + (FN_YL - FN_YH), Ylo + so);
    }
    CP_COMMIT();
    // ---- stage W hi/lo: [128 c][128 ci]
#pragma unroll
    for (int i = 0; i < 16; i++) {
        int idx = tid + i * 256;
        int r = idx >> 5, c4 = idx & 31;
        float4 v = *(const float4*)&Ww[(size_t)(c0 + r) * CI + 4 * c4];
        uint2 H, L;
        H.x = pk(v.x, v.y); H.y = pk(v.z, v.w);
        L.x = pk(resid(v.x), resid(v.y)); L.y = pk(resid(v.z), resid(v.w));
        uint32_t o = (uint32_t)r * FN_PITCH + 8u * (uint32_t)c4;
        *(uint2*)(fsm + FN_WH + o) = H;
        *(uint2*)(fsm + FN_WL + o) = L;
    }
    CP_WAIT0();
    __syncthreads();

    const int lm = lane & 7, mid = lane >> 3;
    const int arow = (mid & 1) * 8 + lm, acolB = (mid >> 1) * 16;
    const int brow = (mid >> 1) * 8 + lm, bcolB = (mid & 1) * 16;

    // preload all A fragments (warp's 16 c-rows, K=128)
    uint32_t ah[8][4], al[8][4];
    const uint32_t aB = sb + FN_WH + (uint32_t)(wid * 16 + arow) * FN_PITCH + acolB;
#pragma unroll
    for (int kk = 0; kk < 8; kk++) {
        LDM_X4(ah[kk], aB + 32u * kk);
        LDM_X4(al[kk], aB + (FN_WL - FN_WH) + 32u * kk);
    }

    float yacc[16][4];
#pragma unroll
    for (int t = 0; t < 16; t++)
#pragma unroll
        for (int j = 0; j < 4; j++) yacc[t][j] = 0.f;

#pragma unroll
    for (int np = 0; np < 8; np++) {
        const uint32_t bB = sb + FN_YH +
            (uint32_t)(np * 16 + brow) * FN_PITCH + bcolB;
#pragma unroll
        for (int kk = 0; kk < 8; kk++) {
            uint32_t bh[4], bl[4];
            LDM_X4(bh, bB + 32u * kk);
            LDM_X4(bl, bB + (FN_YL - FN_YH) + 32u * kk);
            mma6(yacc[2 * np], yacc[2 * np + 1], ah[kk], al[kk], bh, bl);
        }
    }

    // ---- epilogue: BN
    const int gq = lane >> 2, tig = lane & 3;
    const int cA = c0 + wid * 16 + gq;
    const int cB = cA + 8;
    float iA = rsqrtf(var[cA] + 1e-5f);
    float A0 = gamma[cA] * iA, B0 = beta[cA] - mean[cA] * A0;
    float iB = rsqrtf(var[cB] + 1e-5f);
    float A1 = gamma[cB] * iB, B1 = beta[cB] - mean[cB] * A1;

#pragma unroll
    for (int t = 0; t < 16; t++) {
        int n = n0 + (t >> 1) * 16 + (t & 1) * 8 + 2 * tig;
        size_t o0 = ((size_t)bb * C_IN + cA) * NPIX + n;
        size_t o1 = ((size_t)bb * C_IN + cB) * NPIX + n;
        *(float2*)(out + o0) = make_float2(yacc[t][0] * A0 + B0,
                                           yacc[t][1] * A0 + B0);
        *(float2*)(out + o1) = make_float2(yacc[t][2] * A1 + B1,
                                           yacc[t][3] * A1 + B1);
    }
}

// ---------------------------------------------------------------------------
// Launch
// ---------------------------------------------------------------------------
extern "C" void kernel_launch(void* const* d_in, const int* in_sizes, int n_in,
                              void* d_out, int out_size) {
    const float* a       = (const float*)d_in[0];
    const float* b       = (const float*)d_in[1];
    const float* theta_w = (const float*)d_in[2];
    const float* theta_b = (const float*)d_in[3];
    const float* phi_w   = (const float*)d_in[4];
    const float* phi_b   = (const float*)d_in[5];
    const float* g_w     = (const float*)d_in[6];
    const float* g_b     = (const float*)d_in[7];
    const float* W_w     = (const float*)d_in[8];
    const float* bn_g    = (const float*)d_in[9];
    const float* bn_be   = (const float*)d_in[10];
    const float* bn_m    = (const float*)d_in[11];
    const float* bn_v    = (const float*)d_in[12];
    float* out = (float*)d_out;

    __nv_bfloat16 *Thi, *Tlo, *Phh, *Phl, *Ghi, *Glo, *Yhi, *Ylo;
    cudaGetSymbolAddress((void**)&Thi, g_Thi);
    cudaGetSymbolAddress((void**)&Tlo, g_Tlo);
    cudaGetSymbolAddress((void**)&Phh, g_Phh);
    cudaGetSymbolAddress((void**)&Phl, g_Phl);
    cudaGetSymbolAddress((void**)&Ghi, g_Ghi);
    cudaGetSymbolAddress((void**)&Glo, g_Glo);
    cudaGetSymbolAddress((void**)&Yhi, g_Yhi);
    cudaGetSymbolAddress((void**)&Ylo, g_Ylo);

    cudaFuncSetAttribute(proj_mma_kernel<1>,
                         cudaFuncAttributeMaxDynamicSharedMemorySize, PJ_SMEM);
    cudaFuncSetAttribute(proj_mma_kernel<0>,
                         cudaFuncAttributeMaxDynamicSharedMemorySize, PJ_SMEM);
    cudaFuncSetAttribute(attn_hmma_kernel,
                         cudaFuncAttributeMaxDynamicSharedMemorySize, SMEM_BYTES);
    cudaFuncSetAttribute(final_mma_kernel,
                         cudaFuncAttributeMaxDynamicSharedMemorySize, FN_SMEM);

    dim3 projGrid(NPIX / 64, BATCH);
    proj_mma_kernel<1><<<projGrid, 256, PJ_SMEM>>>(a, theta_w, theta_b, Thi, Tlo);
    proj_mma_kernel<1><<<projGrid, 256, PJ_SMEM>>>(b, phi_w,   phi_b,   Phh, Phl);
    proj_mma_kernel<0><<<projGrid, 256, PJ_SMEM>>>(b, g_w,     g_b,     Ghi, Glo);

    dim3 attnGrid(NPIX / NT, BATCH);
    attn_hmma_kernel<<<attnGrid, 256, SMEM_BYTES>>>(Thi, Tlo, Phh, Phl,
                                                    Ghi, Glo, Yhi, Ylo);

    dim3 finGrid(NPIX / 128, C_IN / 128, BATCH);
    final_mma_kernel<<<finGrid, 256, FN_SMEM>>>(Yhi, Ylo, W_w, bn_g, bn_be,
                                                bn_m, bn_v, out);
}